// round 6
// baseline (speedup 1.0000x reference)
#include <cuda_runtime.h>

#define N_SAMPLES 16384
#define DIM       1024
#define CHUNKS    (DIM / 4 / 32)        // 8 float4-chunks per lane
#define MARGIN    1.0f
#define EPSF      1e-6f
#define BLOCK     256
#define WARPS     (BLOCK / 32)          // 8 samples per block
#define GRID      (N_SAMPLES / WARPS)   // 2048 blocks

__device__ double g_acc;      // zero at load; reset by last block each call
__device__ unsigned g_count;

__device__ __forceinline__ float dot4(float4 u, float4 v) {
    return u.x*v.x + u.y*v.y + u.z*v.z + u.w*v.w;
}

__global__ __launch_bounds__(BLOCK)
void cl_dot_kernel(const float* __restrict__ emb,
                   const int* __restrict__ pos_idx,
                   const int* __restrict__ neg_idx,
                   float* __restrict__ out)
{
    const int wid  = threadIdx.x >> 5;
    const int lane = threadIdx.x & 31;
    const int i    = blockIdx.x * WARPS + wid;   // sample for this warp

    const int p = pos_idx[i];
    const int n = neg_idx[i];

    const float4* ra = (const float4*)(emb + (size_t)i * DIM);
    const float4* rb = (const float4*)(emb + (size_t)p * DIM);
    const float4* rc = (const float4*)(emb + (size_t)n * DIM);

    // Single streaming pass: 5 dot-product accumulators, FULL 1024-dim row.
    float sa = 0.f, sb = 0.f, sc = 0.f, dab = 0.f, dac = 0.f;

    #pragma unroll
    for (int c = 0; c < CHUNKS; c++) {
        const int idx = c * 32 + lane;           // coalesced 512B per chunk-load
        float4 a = ra[idx];
        float4 b = rb[idx];
        float4 cc = rc[idx];
        sa  += dot4(a, a);
        sb  += dot4(b, b);
        sc  += dot4(cc, cc);
        dab += dot4(a, b);
        dac += dot4(a, cc);
    }

    #pragma unroll
    for (int o = 16; o > 0; o >>= 1) {
        sa  += __shfl_xor_sync(0xffffffffu, sa,  o);
        sb  += __shfl_xor_sync(0xffffffffu, sb,  o);
        sc  += __shfl_xor_sync(0xffffffffu, sc,  o);
        dab += __shfl_xor_sync(0xffffffffu, dab, o);
        dac += __shfl_xor_sync(0xffffffffu, dac, o);
    }

    __shared__ double warp_loss[WARPS];
    if (lane == 0) {
        // F.normalize: 1/max(||x||, eps)
        const float ia = 1.0f / fmaxf(sqrtf(sa), EPSF);
        const float ib = 1.0f / fmaxf(sqrtf(sb), EPSF);
        const float ic = 1.0f / fmaxf(sqrtf(sc), EPSF);

        // ||u - v + eps||^2 expanded (eps cross term ~2e-6, statistically 0 -> dropped)
        const float de2 = (float)DIM * EPSF * EPSF;
        float dp = sa*ia*ia + sb*ib*ib - 2.0f*dab*ia*ib + de2;
        float dn = sa*ia*ia + sc*ic*ic - 2.0f*dac*ia*ic + de2;
        dp = fmaxf(dp, 0.0f);
        dn = fmaxf(dn, 0.0f);

        const float d_pos = sqrtf(dp) + EPSF;    // pairwise_distance + module eps
        const float d_neg = sqrtf(dn) + EPSF;

        const float lp = d_pos * d_pos;
        const float tn = fmaxf(MARGIN - d_neg, EPSF);
        warp_loss[wid] = (double)(lp + tn * tn);
    }
    __syncthreads();

    if (threadIdx.x == 0) {
        double blk = 0.0;
        #pragma unroll
        for (int w = 0; w < WARPS; w++) blk += warp_loss[w];

        atomicAdd(&g_acc, blk);
        __threadfence();
        unsigned done = atomicAdd(&g_count, 1u);
        if (done == GRID - 1u) {
            out[0] = (float)(g_acc / (2.0 * (double)N_SAMPLES));
            g_acc = 0.0;      // reset for next graph replay
            g_count = 0u;
            __threadfence();
        }
    }
}

extern "C" void kernel_launch(void* const* d_in, const int* in_sizes, int n_in,
                              void* d_out, int out_size)
{
    const float* emb = (const float*)d_in[0];
    // d_in[1] = labels (int32) — unused by the loss
    const int*   pos = (const int*)d_in[2];
    const int*   neg = (const int*)d_in[3];
    float* out = (float*)d_out;

    cl_dot_kernel<<<GRID, BLOCK>>>(emb, pos, neg, out);
}